// round 5
// baseline (speedup 1.0000x reference)
#include <cuda_runtime.h>

#define WIDTH  2048
#define HEIGHT 2048
#define HW (2048 * 2048)
#define KS  97
#define RAD 48
#define RV  16          // vertical outputs per thread
#define RH  16          // horizontal outputs per thread
#define PADW 127        // zero-padded weight table: index = tap + 15, tap in [-15, 111]

// ---------------- device scratch (no allocations allowed) ----------------
__device__ float2 g_wv[PADW + 1];   // vertical weights  (ch0: sigma0, ch1: sigma1), zero-padded
__device__ float2 g_wh[PADW + 1];   // horizontal weights * alpha, zero-padded
__device__ float2 g_tmp[HW];        // vertically blurred field, interleaved (ch0, ch1)

// ---------------- packed fp32x2 FMA (sm_103a FFMA2) ----------------
__device__ __forceinline__ unsigned long long f2u(float2 v) {
    union { float2 f; unsigned long long u; } x; x.f = v; return x.u;
}
__device__ __forceinline__ float2 u2f(unsigned long long u) {
    union { float2 f; unsigned long long u; } x; x.u = u; return x.f;
}
__device__ __forceinline__ float2 ffma2(float2 a, float2 b, float2 c) {
    unsigned long long d;
    asm("fma.rn.f32x2 %0, %1, %2, %3;"
        : "=l"(d) : "l"(f2u(a)), "l"(f2u(b)), "l"(f2u(c)));
    return u2f(d);
}

// ---------------- K0: build Gaussian weight tables ----------------
__global__ void weights_kernel(const float* __restrict__ log_sigma,
                               const float* __restrict__ log_alpha) {
    __shared__ float e0s[KS], e1s[KS];
    __shared__ float sums[2];
    int t = threadIdx.x;
    float s0 = expf(log_sigma[0]);
    float s1 = expf(log_sigma[1]);
    if (t < KS) {
        float x = (float)(t - KS / 2);
        e0s[t] = expf(-x * x / (2.0f * s0 * s0));
        e1s[t] = expf(-x * x / (2.0f * s1 * s1));
    }
    __syncthreads();
    if (t == 0) {
        float a = 0.f, b = 0.f;
        for (int i = 0; i < KS; i++) { a += e0s[i]; b += e1s[i]; }
        sums[0] = a; sums[1] = b;
    }
    __syncthreads();
    float a0 = expf(log_alpha[0]);
    float a1 = expf(log_alpha[1]);
    if (t <= PADW) {
        float2 wv = make_float2(0.f, 0.f);
        float2 wh = make_float2(0.f, 0.f);
        int j = t - 15;                 // tap index
        if (j >= 0 && j < KS) {
            wv.x = e0s[j] / sums[0];
            wv.y = e1s[j] / sums[1];
            wh.x = wv.x * a0;
            wh.y = wv.y * a1;
        }
        g_wv[t] = wv;
        g_wh[t] = wh;
    }
}

// ---------------- K1: vertical blur (both channels packed) ----------------
// d = 2*d_rand - 1, zero padding outside [0,H). Each thread: 16 consecutive rows
// at one x, register accumulators, one load pair per input row.
__global__ void __launch_bounds__(256) vblur_kernel(const float* __restrict__ drand) {
    __shared__ float2 sw[PADW];
    int tid = threadIdx.x;
    if (tid < PADW) sw[tid] = g_wv[tid];
    __syncthreads();

    int x  = blockIdx.x * 256 + tid;
    int y0 = blockIdx.y * RV;

    float2 acc[RV];
#pragma unroll
    for (int r = 0; r < RV; r++) acc[r] = make_float2(0.f, 0.f);

    const float* d0 = drand;
    const float* d1 = drand + HW;

#pragma unroll 1
    for (int s = 0; s < RV + 2 * RAD; ++s) {
        int iy = y0 - RAD + s;
        float2 v = make_float2(0.f, 0.f);
        if (iy >= 0 && iy < HEIGHT) {
            size_t off = (size_t)iy * WIDTH + x;
            v.x = 2.0f * __ldg(d0 + off) - 1.0f;
            v.y = 2.0f * __ldg(d1 + off) - 1.0f;
        }
        const float2* wp = sw + s;      // weight for r is wp[15 - r] (immediate offsets)
#pragma unroll
        for (int r = 0; r < RV; r++) {
            acc[r] = ffma2(wp[15 - r], v, acc[r]);
        }
    }
#pragma unroll
    for (int r = 0; r < RV; r++) {
        g_tmp[(size_t)(y0 + r) * WIDTH + x] = acc[r];
    }
}

// ---------------- K2: horizontal blur + bilinear sample, fused ----------------
// One block per row. Skewed SMEM (idx + idx>>4) kills the 128B-stride bank
// conflicts from 16-consecutive-x ownership. Outputs staged in SMEM (aliased on
// the row buffer) and written coalesced.
#define SROW_ELEMS 2280                      // f(2143)=2276 < 2280  (float2)
#define SOUT_PITCH 2176                      // f(2047)=2174 < 2176  (float)
#define BUF_BYTES  (4 * SOUT_PITCH * 4)      // 34816 >= SROW_ELEMS*8 (18240)

__global__ void __launch_bounds__(128) hblur_sample_kernel(
    const float* __restrict__ img, const float* __restrict__ msk,
    float* __restrict__ out) {
    __shared__ float2 sw[PADW];
    __shared__ __align__(16) unsigned char buf[BUF_BYTES];
    float2* srow = (float2*)buf;
    float*  sout = (float*)buf;

    int tid = threadIdx.x;
    int y   = blockIdx.x;

    if (tid < PADW) sw[tid] = g_wh[tid];

    // load row with zero halo, skewed
    for (int p = tid; p < WIDTH + 2 * RAD; p += 128) {
        int xx = p - RAD;
        float2 v = make_float2(0.f, 0.f);
        if (xx >= 0 && xx < WIDTH) v = g_tmp[(size_t)y * WIDTH + xx];
        srow[p + (p >> 4)] = v;
    }
    __syncthreads();

    int x0 = tid * RH;
    float2 acc[RH];
#pragma unroll
    for (int r = 0; r < RH; r++) acc[r] = make_float2(0.f, 0.f);

#pragma unroll 1
    for (int s = 0; s < RH + 2 * RAD; ++s) {
        int p = x0 + s;
        float2 v = srow[p + (p >> 4)];
        const float2* wp = sw + s;
#pragma unroll
        for (int r = 0; r < RH; r++) {
            acc[r] = ffma2(wp[15 - r], v, acc[r]);
        }
    }

    __syncthreads();   // done reading srow; buf will be reused as sout

    const float gy = (float)y * (2.0f / (HEIGHT - 1)) - 1.0f;

#pragma unroll
    for (int r = 0; r < RH; r++) {
        int x = x0 + r;
        float gx = (float)x * (2.0f / (WIDTH - 1)) - 1.0f;
        // reference: x-coord gets blurred ch0 (dy), y-coord gets blurred ch1 (dx)
        float sx = fminf(fmaxf(gx + acc[r].x, -1.0f), 1.0f);
        float sy = fminf(fmaxf(gy + acc[r].y, -1.0f), 1.0f);
        float px = (sx + 1.0f) * 0.5f * (float)(WIDTH - 1);
        float py = (sy + 1.0f) * 0.5f * (float)(HEIGHT - 1);
        float fx = floorf(px), fy = floorf(py);
        float wx = px - fx,    wy = py - fy;
        int ix0 = (int)fx;
        int iy0 = (int)fy;
        int ix1 = min(ix0 + 1, WIDTH - 1);
        int iy1 = min(iy0 + 1, HEIGHT - 1);
        size_t o00 = (size_t)iy0 * WIDTH + ix0;
        size_t o01 = (size_t)iy0 * WIDTH + ix1;
        size_t o10 = (size_t)iy1 * WIDTH + ix0;
        size_t o11 = (size_t)iy1 * WIDTH + ix1;
        int xs = x + (x >> 4);
#pragma unroll
        for (int c = 0; c < 4; c++) {
            const float* src = (c < 3) ? (img + (size_t)c * HW) : msk;
            float v00 = __ldg(src + o00);
            float v01 = __ldg(src + o01);
            float v10 = __ldg(src + o10);
            float v11 = __ldg(src + o11);
            float top = v00 * (1.0f - wx) + v01 * wx;
            float bot = v10 * (1.0f - wx) + v11 * wx;
            sout[c * SOUT_PITCH + xs] = top * (1.0f - wy) + bot * wy;
        }
    }

    __syncthreads();

    size_t rowoff = (size_t)y * WIDTH;
    for (int x = tid; x < WIDTH; x += 128) {
        int xs = x + (x >> 4);
        out[0 * (size_t)HW + rowoff + x] = sout[0 * SOUT_PITCH + xs];
        out[1 * (size_t)HW + rowoff + x] = sout[1 * SOUT_PITCH + xs];
        out[2 * (size_t)HW + rowoff + x] = sout[2 * SOUT_PITCH + xs];
        out[3 * (size_t)HW + rowoff + x] = sout[3 * SOUT_PITCH + xs];
    }
}

// ---------------- launch ----------------
extern "C" void kernel_launch(void* const* d_in, const int* in_sizes, int n_in,
                              void* d_out, int out_size) {
    const float* image     = (const float*)d_in[0];  // (3, H, W)
    const float* mask      = (const float*)d_in[1];  // (1, H, W)
    const float* drand     = (const float*)d_in[2];  // (1, 2, H, W)
    const float* log_sigma = (const float*)d_in[3];  // (2,)
    const float* log_alpha = (const float*)d_in[4];  // (2,)
    float* out = (float*)d_out;                      // img(3HW) then mask(HW)

    weights_kernel<<<1, 128>>>(log_sigma, log_alpha);
    vblur_kernel<<<dim3(WIDTH / 256, HEIGHT / RV), 256>>>(drand);
    hblur_sample_kernel<<<HEIGHT, 128>>>(image, mask, out);
}

// round 7
// speedup vs baseline: 1.0118x; 1.0118x over previous
#include <cuda_runtime.h>

#define WIDTH  2048
#define HEIGHT 2048
#define HW (2048 * 2048)
#define KS  97
#define RAD 48
#define R   16          // outputs per thread (both passes)

// ---------------- device scratch (no allocations allowed) ----------------
__device__ float2 g_wv[KS];    // vertical weights  (ch0: sigma0, ch1: sigma1)
__device__ float2 g_wh[KS];    // horizontal weights * alpha
__device__ float2 g_tmp[HW];   // vertically blurred field, interleaved (ch0, ch1)

// ---------------- packed fp32x2 FMA (sm_103a FFMA2) ----------------
__device__ __forceinline__ unsigned long long f2u(float2 v) {
    union { float2 f; unsigned long long u; } x; x.f = v; return x.u;
}
__device__ __forceinline__ float2 u2f(unsigned long long u) {
    union { float2 f; unsigned long long u; } x; x.u = u; return x.f;
}
__device__ __forceinline__ float2 ffma2(float2 a, float2 b, float2 c) {
    unsigned long long d;
    asm("fma.rn.f32x2 %0, %1, %2, %3;"
        : "=l"(d) : "l"(f2u(a)), "l"(f2u(b)), "l"(f2u(c)));
    return u2f(d);
}

// ---------------- K0: build Gaussian weight tables ----------------
__global__ void weights_kernel(const float* __restrict__ log_sigma,
                               const float* __restrict__ log_alpha) {
    __shared__ float e0s[KS], e1s[KS];
    __shared__ float sums[2];
    int t = threadIdx.x;
    float s0 = expf(log_sigma[0]);
    float s1 = expf(log_sigma[1]);
    if (t < KS) {
        float x = (float)(t - KS / 2);
        e0s[t] = expf(-x * x / (2.0f * s0 * s0));
        e1s[t] = expf(-x * x / (2.0f * s1 * s1));
    }
    __syncthreads();
    if (t == 0) {
        float a = 0.f, b = 0.f;
        for (int i = 0; i < KS; i++) { a += e0s[i]; b += e1s[i]; }
        sums[0] = a; sums[1] = b;
    }
    __syncthreads();
    float a0 = expf(log_alpha[0]);
    float a1 = expf(log_alpha[1]);
    if (t < KS) {
        float2 wv, wh;
        wv.x = e0s[t] / sums[0];
        wv.y = e1s[t] / sums[1];
        wh.x = wv.x * a0;
        wh.y = wv.y * a1;
        g_wv[t] = wv;
        g_wh[t] = wh;
    }
}

// ================= K1: vertical blur (both channels packed) =================
// 97-tap FIR, 16 outputs/thread, 32-slot register window over inputs.
// Window invariant: input row index m lives in win[m & 31]. The refill for
// slot (J+jj)&31 is issued right after that slot's last read, ~256 FMA-slots
// before its first use in the next block -> MLP=16, gmem latency hidden.
__global__ void __launch_bounds__(256) vblur_kernel(const float* __restrict__ drand) {
    __shared__ float2 sw[KS];
    int tid = threadIdx.x;
    if (tid < KS) sw[tid] = g_wv[tid];
    __syncthreads();

    int x  = blockIdx.x * 256 + tid;
    int y0 = blockIdx.y * R;

    const float* d0 = drand;
    const float* d1 = drand + HW;

    float2 acc[R];
#pragma unroll
    for (int r = 0; r < R; r++) acc[r] = make_float2(0.f, 0.f);

    float2 win[32];
#pragma unroll
    for (int k = 0; k < 32; k++) {
        int iy = y0 - RAD + k;
        float2 v = make_float2(0.f, 0.f);
        if (iy >= 0 && iy < HEIGHT) {
            size_t off = (size_t)iy * WIDTH + x;
            float2 d = make_float2(__ldg(d0 + off), __ldg(d1 + off));
            v = ffma2(make_float2(2.f, 2.f), d, make_float2(-1.f, -1.f));
        }
        win[k] = v;
    }

#pragma unroll
    for (int J = 0; J < 96; J += 16) {
#pragma unroll
        for (int jj = 0; jj < 16; jj++) {
            const int j = J + jj;
            float2 wj = sw[j];
#pragma unroll
            for (int r = 0; r < R; r++)
                acc[r] = ffma2(wj, win[(j + r) & 31], acc[r]);
            if (J < 80) {
                int iy = y0 - RAD + j + 32;
                float2 v = make_float2(0.f, 0.f);
                if (iy >= 0 && iy < HEIGHT) {
                    size_t off = (size_t)iy * WIDTH + x;
                    float2 d = make_float2(__ldg(d0 + off), __ldg(d1 + off));
                    v = ffma2(make_float2(2.f, 2.f), d, make_float2(-1.f, -1.f));
                }
                win[j & 31] = v;
            }
        }
    }
    {
        float2 w96 = sw[96];
#pragma unroll
        for (int r = 0; r < R; r++)
            acc[r] = ffma2(w96, win[(96 + r) & 31], acc[r]);
    }

#pragma unroll
    for (int r = 0; r < R; r++)
        g_tmp[(size_t)(y0 + r) * WIDTH + x] = acc[r];
}

// ============ K2: horizontal blur + bilinear sample, fused ============
#define SOUT_PITCH 2176                      // sk(2047)=2174 < 2176 (float)
#define BUF_BYTES  (4 * SOUT_PITCH * 4)      // 34816 >= sk(2143)*8+8 = 18216

__device__ __forceinline__ int sk(int p) { return p + (p >> 4); }

__global__ void __launch_bounds__(128) hblur_sample_kernel(
    const float* __restrict__ img, const float* __restrict__ msk,
    float* __restrict__ out) {
    __shared__ float2 sw[KS];
    __shared__ __align__(16) unsigned char buf[BUF_BYTES];
    float2* srow = (float2*)buf;
    float*  sout = (float*)buf;

    int tid = threadIdx.x;
    int y   = blockIdx.x;

    if (tid < KS) sw[tid] = g_wh[tid];

    // load row with zero halo, skewed (conflict-free for the window reads)
    for (int p = tid; p < WIDTH + 2 * RAD; p += 128) {
        int xx = p - RAD;
        float2 v = make_float2(0.f, 0.f);
        if (xx >= 0 && xx < WIDTH) v = g_tmp[(size_t)y * WIDTH + xx];
        srow[sk(p)] = v;
    }
    __syncthreads();

    int x0 = tid * R;
    float2 acc[R];
#pragma unroll
    for (int r = 0; r < R; r++) acc[r] = make_float2(0.f, 0.f);

    float2 win[32];
#pragma unroll
    for (int k = 0; k < 32; k++) win[k] = srow[sk(x0 + k)];

#pragma unroll
    for (int J = 0; J < 96; J += 16) {
#pragma unroll
        for (int jj = 0; jj < 16; jj++) {
            const int j = J + jj;
            float2 wj = sw[j];
#pragma unroll
            for (int r = 0; r < R; r++)
                acc[r] = ffma2(wj, win[(j + r) & 31], acc[r]);
            if (J < 80) win[j & 31] = srow[sk(x0 + j + 32)];
        }
    }
    {
        float2 w96 = sw[96];
#pragma unroll
        for (int r = 0; r < R; r++)
            acc[r] = ffma2(w96, win[(96 + r) & 31], acc[r]);
    }

    __syncthreads();   // done reading srow; buf reused as sout

    const float gy = (float)y * (2.0f / (HEIGHT - 1)) - 1.0f;

#pragma unroll
    for (int r = 0; r < R; r++) {
        int x = x0 + r;
        float gx = (float)x * (2.0f / (WIDTH - 1)) - 1.0f;
        // reference: x-coord gets blurred ch0 (dy), y-coord gets blurred ch1 (dx)
        float sx = fminf(fmaxf(gx + acc[r].x, -1.0f), 1.0f);
        float sy = fminf(fmaxf(gy + acc[r].y, -1.0f), 1.0f);
        float px = (sx + 1.0f) * 0.5f * (float)(WIDTH - 1);
        float py = (sy + 1.0f) * 0.5f * (float)(HEIGHT - 1);
        float fx = floorf(px), fy = floorf(py);
        float wx = px - fx,    wy = py - fy;
        int ix0 = (int)fx;
        int iy0 = (int)fy;
        int ix1 = min(ix0 + 1, WIDTH - 1);
        int iy1 = min(iy0 + 1, HEIGHT - 1);
        size_t o00 = (size_t)iy0 * WIDTH + ix0;
        size_t o01 = (size_t)iy0 * WIDTH + ix1;
        size_t o10 = (size_t)iy1 * WIDTH + ix0;
        size_t o11 = (size_t)iy1 * WIDTH + ix1;
        int xs = sk(x);
#pragma unroll
        for (int c = 0; c < 4; c++) {
            const float* src = (c < 3) ? (img + (size_t)c * HW) : msk;
            float v00 = __ldg(src + o00);
            float v01 = __ldg(src + o01);
            float v10 = __ldg(src + o10);
            float v11 = __ldg(src + o11);
            float top = v00 * (1.0f - wx) + v01 * wx;
            float bot = v10 * (1.0f - wx) + v11 * wx;
            sout[c * SOUT_PITCH + xs] = top * (1.0f - wy) + bot * wy;
        }
    }

    __syncthreads();

    size_t rowoff = (size_t)y * WIDTH;
    for (int x = tid; x < WIDTH; x += 128) {
        int xs = sk(x);
        out[0 * (size_t)HW + rowoff + x] = sout[0 * SOUT_PITCH + xs];
        out[1 * (size_t)HW + rowoff + x] = sout[1 * SOUT_PITCH + xs];
        out[2 * (size_t)HW + rowoff + x] = sout[2 * SOUT_PITCH + xs];
        out[3 * (size_t)HW + rowoff + x] = sout[3 * SOUT_PITCH + xs];
    }
}

// ---------------- launch ----------------
extern "C" void kernel_launch(void* const* d_in, const int* in_sizes, int n_in,
                              void* d_out, int out_size) {
    const float* image     = (const float*)d_in[0];  // (3, H, W)
    const float* mask      = (const float*)d_in[1];  // (1, H, W)
    const float* drand     = (const float*)d_in[2];  // (1, 2, H, W)
    const float* log_sigma = (const float*)d_in[3];  // (2,)
    const float* log_alpha = (const float*)d_in[4];  // (2,)
    float* out = (float*)d_out;                      // img(3HW) then mask(HW)

    weights_kernel<<<1, 128>>>(log_sigma, log_alpha);
    vblur_kernel<<<dim3(WIDTH / 256, HEIGHT / R), 256>>>(drand);
    hblur_sample_kernel<<<HEIGHT, 128>>>(image, mask, out);
}

// round 10
// speedup vs baseline: 1.7080x; 1.6881x over previous
#include <cuda_runtime.h>

#define WIDTH  2048
#define HEIGHT 2048
#define HW (2048 * 2048)
#define KS  97
#define RAD 48
#define R   16          // outputs per thread (both passes)

typedef unsigned long long ull;

// ---------------- device scratch (no allocations allowed) ----------------
__device__ float2 g_wv[KS];    // vertical weights  (ch0: sigma0, ch1: sigma1)
__device__ float2 g_wh[KS];    // horizontal weights * alpha
__device__ float2 g_tmp[HW];   // vertically blurred field, interleaved (ch0, ch1)

// ---------------- packed fp32x2 ops, u64-native (no per-FMA repacking) ------
__device__ __forceinline__ ull packf2(float lo, float hi) {
    ull u;
    asm("mov.b64 %0, {%1, %2};" : "=l"(u) : "f"(lo), "f"(hi));
    return u;
}
__device__ __forceinline__ void unpackf2(ull u, float& lo, float& hi) {
    asm("mov.b64 {%0, %1}, %2;" : "=f"(lo), "=f"(hi) : "l"(u));
}
__device__ __forceinline__ ull ffma2u(ull a, ull b, ull c) {
    ull d;
    asm("fma.rn.f32x2 %0, %1, %2, %3;" : "=l"(d) : "l"(a), "l"(b), "l"(c));
    return d;
}

// ---------------- K0: build Gaussian weight tables ----------------
__global__ void weights_kernel(const float* __restrict__ log_sigma,
                               const float* __restrict__ log_alpha) {
    __shared__ float e0s[KS], e1s[KS];
    __shared__ float sums[2];
    int t = threadIdx.x;
    float s0 = expf(log_sigma[0]);
    float s1 = expf(log_sigma[1]);
    if (t < KS) {
        float x = (float)(t - KS / 2);
        e0s[t] = expf(-x * x / (2.0f * s0 * s0));
        e1s[t] = expf(-x * x / (2.0f * s1 * s1));
    }
    __syncthreads();
    if (t == 0) {
        float a = 0.f, b = 0.f;
        for (int i = 0; i < KS; i++) { a += e0s[i]; b += e1s[i]; }
        sums[0] = a; sums[1] = b;
    }
    __syncthreads();
    float a0 = expf(log_alpha[0]);
    float a1 = expf(log_alpha[1]);
    if (t < KS) {
        float2 wv, wh;
        wv.x = e0s[t] / sums[0];
        wv.y = e1s[t] / sums[1];
        wh.x = wv.x * a0;
        wh.y = wv.y * a1;
        g_wv[t] = wv;
        g_wh[t] = wh;
    }
}

// ================= K1: vertical blur (both channels packed) =================
// 97-tap FIR, 16 outputs/thread, 32-slot u64 register window over inputs.
__global__ void __launch_bounds__(256) vblur_kernel(const float* __restrict__ drand) {
    __shared__ ull sw[KS];
    int tid = threadIdx.x;
    if (tid < KS) sw[tid] = ((const ull*)g_wv)[tid];
    __syncthreads();

    int x  = blockIdx.x * 256 + tid;
    int y0 = blockIdx.y * R;

    const float* d0 = drand;
    const float* d1 = drand + HW;
    const ull c_two  = packf2(2.f, 2.f);
    const ull c_mone = packf2(-1.f, -1.f);

    ull acc[R];
#pragma unroll
    for (int r = 0; r < R; r++) acc[r] = 0ull;   // packed (0,0)

    ull win[32];
#pragma unroll
    for (int k = 0; k < 32; k++) {
        int iy = y0 - RAD + k;
        ull v = 0ull;
        if ((unsigned)iy < (unsigned)HEIGHT) {
            size_t off = (size_t)iy * WIDTH + x;
            v = ffma2u(c_two, packf2(__ldg(d0 + off), __ldg(d1 + off)), c_mone);
        }
        win[k] = v;
    }

#pragma unroll
    for (int J = 0; J < 96; J += 16) {
#pragma unroll
        for (int jj = 0; jj < 16; jj++) {
            const int j = J + jj;
            ull wj = sw[j];
#pragma unroll
            for (int r = 0; r < R; r++)
                acc[r] = ffma2u(wj, win[(j + r) & 31], acc[r]);
            if (J < 80) {
                int iy = y0 - RAD + j + 32;
                ull v = 0ull;
                if ((unsigned)iy < (unsigned)HEIGHT) {
                    size_t off = (size_t)iy * WIDTH + x;
                    v = ffma2u(c_two, packf2(__ldg(d0 + off), __ldg(d1 + off)), c_mone);
                }
                win[j & 31] = v;
            }
        }
    }
    {
        ull w96 = sw[96];
#pragma unroll
        for (int r = 0; r < R; r++)
            acc[r] = ffma2u(w96, win[(96 + r) & 31], acc[r]);
    }

#pragma unroll
    for (int r = 0; r < R; r++)
        ((ull*)g_tmp)[(size_t)(y0 + r) * WIDTH + x] = acc[r];
}

// ============ K2: horizontal blur + bilinear sample, fused ============
// SoA skewed smem rows; skew stride 17 (odd bank stride) -> conflict-free for
// both the stride-16 conv window reads and the stride-1 sampler reads. After
// the conv, the blurred field is staged back into the same smem and the
// sampling phase remaps threads to x = tid + k*128 so gather LDGs and output
// STGs are lane-consecutive (few L1tex wavefronts per instruction).
__device__ __forceinline__ int sk(int p) { return p + (p >> 4); }
#define SKN 2280   // sk(2143)=2276 < 2280

__global__ void __launch_bounds__(128) hblur_sample_kernel(
    const float* __restrict__ img, const float* __restrict__ msk,
    float* __restrict__ out) {
    __shared__ ull   sw[KS];
    __shared__ float sfx[SKN];
    __shared__ float sfy[SKN];

    int tid = threadIdx.x;
    int y   = blockIdx.x;

    if (tid < KS) sw[tid] = ((const ull*)g_wh)[tid];

    // Phase 1: load row with zero halo into SoA skewed smem
    for (int p = tid; p < WIDTH + 2 * RAD; p += 128) {
        int xx = p - RAD;
        float2 v = make_float2(0.f, 0.f);
        if ((unsigned)xx < (unsigned)WIDTH) v = g_tmp[(size_t)y * WIDTH + xx];
        int ps = sk(p);
        sfx[ps] = v.x;
        sfy[ps] = v.y;
    }
    __syncthreads();

    // Phase 2: 97-tap conv, 32-slot register window
    int x0 = tid * R;
    ull acc[R];
#pragma unroll
    for (int r = 0; r < R; r++) acc[r] = 0ull;

    ull win[32];
#pragma unroll
    for (int k = 0; k < 32; k++) {
        int ps = sk(x0 + k);
        win[k] = packf2(sfx[ps], sfy[ps]);
    }

#pragma unroll
    for (int J = 0; J < 96; J += 16) {
#pragma unroll
        for (int jj = 0; jj < 16; jj++) {
            const int j = J + jj;
            ull wj = sw[j];
#pragma unroll
            for (int r = 0; r < R; r++)
                acc[r] = ffma2u(wj, win[(j + r) & 31], acc[r]);
            if (J < 80) {
                int ps = sk(x0 + j + 32);
                win[j & 31] = packf2(sfx[ps], sfy[ps]);
            }
        }
    }
    {
        ull w96 = sw[96];
#pragma unroll
        for (int r = 0; r < R; r++)
            acc[r] = ffma2u(w96, win[(96 + r) & 31], acc[r]);
    }

    __syncthreads();   // all conv reads of sfx/sfy done

    // Phase 3: stage blurred field back (index by x now, no halo)
#pragma unroll
    for (int r = 0; r < R; r++) {
        float fx_, fy_;
        unpackf2(acc[r], fx_, fy_);
        int ps = sk(x0 + r);
        sfx[ps] = fx_;
        sfy[ps] = fy_;
    }
    __syncthreads();

    // Phase 4: bilinear sample, lane-consecutive x -> coalesced gathers/stores
    const float gy = (float)y * (2.0f / (HEIGHT - 1)) - 1.0f;
    size_t rowoff = (size_t)y * WIDTH;

#pragma unroll 1
    for (int k = 0; k < R; k++) {
        int x = tid + k * 128;
        int ps = sk(x);
        float dxf = sfx[ps];
        float dyf = sfy[ps];
        float gx = (float)x * (2.0f / (WIDTH - 1)) - 1.0f;
        // reference: x-coord gets blurred ch0 (dy), y-coord gets blurred ch1 (dx)
        float sx = fminf(fmaxf(gx + dxf, -1.0f), 1.0f);
        float sy = fminf(fmaxf(gy + dyf, -1.0f), 1.0f);
        float px = (sx + 1.0f) * 0.5f * (float)(WIDTH - 1);
        float py = (sy + 1.0f) * 0.5f * (float)(HEIGHT - 1);
        float fx = floorf(px), fy = floorf(py);
        float wx = px - fx,    wy = py - fy;
        int ix0 = (int)fx;
        int iy0 = (int)fy;
        int ix1 = min(ix0 + 1, WIDTH - 1);
        int iy1 = min(iy0 + 1, HEIGHT - 1);
        size_t o00 = (size_t)iy0 * WIDTH + ix0;
        size_t o01 = (size_t)iy0 * WIDTH + ix1;
        size_t o10 = (size_t)iy1 * WIDTH + ix0;
        size_t o11 = (size_t)iy1 * WIDTH + ix1;
#pragma unroll
        for (int c = 0; c < 4; c++) {
            const float* src = (c < 3) ? (img + (size_t)c * HW) : msk;
            float v00 = __ldg(src + o00);
            float v01 = __ldg(src + o01);
            float v10 = __ldg(src + o10);
            float v11 = __ldg(src + o11);
            float top = v00 * (1.0f - wx) + v01 * wx;
            float bot = v10 * (1.0f - wx) + v11 * wx;
            out[(size_t)c * HW + rowoff + x] = top * (1.0f - wy) + bot * wy;
        }
    }
}

// ---------------- launch ----------------
extern "C" void kernel_launch(void* const* d_in, const int* in_sizes, int n_in,
                              void* d_out, int out_size) {
    const float* image     = (const float*)d_in[0];  // (3, H, W)
    const float* mask      = (const float*)d_in[1];  // (1, H, W)
    const float* drand     = (const float*)d_in[2];  // (1, 2, H, W)
    const float* log_sigma = (const float*)d_in[3];  // (2,)
    const float* log_alpha = (const float*)d_in[4];  // (2,)
    float* out = (float*)d_out;                      // img(3HW) then mask(HW)

    weights_kernel<<<1, 128>>>(log_sigma, log_alpha);
    vblur_kernel<<<dim3(WIDTH / 256, HEIGHT / R), 256>>>(drand);
    hblur_sample_kernel<<<HEIGHT, 128>>>(image, mask, out);
}

// round 11
// speedup vs baseline: 1.7229x; 1.0087x over previous
#include <cuda_runtime.h>

#define WIDTH  2048
#define HEIGHT 2048
#define HW (2048 * 2048)
#define KS  97
#define RAD 48
#define R   16          // outputs per thread (both passes)

typedef unsigned long long ull;

// ---------------- device scratch (no allocations allowed) ----------------
__device__ float2 g_tmp[HW];   // vertically blurred field, interleaved (ch0, ch1)

// ---------------- packed fp32x2 ops, u64-native (no per-FMA repacking) ------
__device__ __forceinline__ ull packf2(float lo, float hi) {
    ull u;
    asm("mov.b64 %0, {%1, %2};" : "=l"(u) : "f"(lo), "f"(hi));
    return u;
}
__device__ __forceinline__ void unpackf2(ull u, float& lo, float& hi) {
    asm("mov.b64 {%0, %1}, %2;" : "=f"(lo), "=f"(hi) : "l"(u));
}
__device__ __forceinline__ ull ffma2u(ull a, ull b, ull c) {
    ull d;
    asm("fma.rn.f32x2 %0, %1, %2, %3;" : "=l"(d) : "l"(a), "l"(b), "l"(c));
    return d;
}

// ---------------- inline weight table build (per-block, deterministic) ------
// Exactly the arithmetic of the old weights_kernel: g=exp(-x^2/(2s^2)),
// w=g/sum, optionally *exp(log_alpha). Two prologue __syncthreads only.
__device__ __forceinline__ void build_weights(
    ull* sw, const float* __restrict__ log_sigma, const float* __restrict__ log_alpha,
    bool mul_alpha, float* e0s, float* e1s, float* sums) {
    int t = threadIdx.x;
    float s0 = expf(log_sigma[0]);
    float s1 = expf(log_sigma[1]);
    if (t < KS) {
        float x = (float)(t - KS / 2);
        e0s[t] = expf(-x * x / (2.0f * s0 * s0));
        e1s[t] = expf(-x * x / (2.0f * s1 * s1));
    }
    __syncthreads();
    if (t == 0) {
        float a = 0.f, b = 0.f;
        for (int i = 0; i < KS; i++) { a += e0s[i]; b += e1s[i]; }
        sums[0] = a; sums[1] = b;
    }
    __syncthreads();
    if (t < KS) {
        float w0 = e0s[t] / sums[0];
        float w1 = e1s[t] / sums[1];
        if (mul_alpha) {
            w0 *= expf(log_alpha[0]);
            w1 *= expf(log_alpha[1]);
        }
        sw[t] = packf2(w0, w1);
    }
    __syncthreads();
}

// ================= K1: vertical blur (both channels packed) =================
// 97-tap FIR, 16 outputs/thread, 32-slot u64 register window over inputs.
__global__ void __launch_bounds__(256) vblur_kernel(
    const float* __restrict__ drand,
    const float* __restrict__ log_sigma, const float* __restrict__ log_alpha) {
    __shared__ ull sw[KS];
    __shared__ float e0s[KS], e1s[KS], sums[2];
    build_weights(sw, log_sigma, log_alpha, false, e0s, e1s, sums);

    int tid = threadIdx.x;
    int x  = blockIdx.x * 256 + tid;
    int y0 = blockIdx.y * R;

    const float* d0 = drand;
    const float* d1 = drand + HW;
    const ull c_two  = packf2(2.f, 2.f);
    const ull c_mone = packf2(-1.f, -1.f);

    ull acc[R];
#pragma unroll
    for (int r = 0; r < R; r++) acc[r] = 0ull;   // packed (0,0)

    ull win[32];
#pragma unroll
    for (int k = 0; k < 32; k++) {
        int iy = y0 - RAD + k;
        ull v = 0ull;
        if ((unsigned)iy < (unsigned)HEIGHT) {
            size_t off = (size_t)iy * WIDTH + x;
            v = ffma2u(c_two, packf2(__ldg(d0 + off), __ldg(d1 + off)), c_mone);
        }
        win[k] = v;
    }

#pragma unroll
    for (int J = 0; J < 96; J += 16) {
#pragma unroll
        for (int jj = 0; jj < 16; jj++) {
            const int j = J + jj;
            ull wj = sw[j];
#pragma unroll
            for (int r = 0; r < R; r++)
                acc[r] = ffma2u(wj, win[(j + r) & 31], acc[r]);
            if (J < 80) {
                int iy = y0 - RAD + j + 32;
                ull v = 0ull;
                if ((unsigned)iy < (unsigned)HEIGHT) {
                    size_t off = (size_t)iy * WIDTH + x;
                    v = ffma2u(c_two, packf2(__ldg(d0 + off), __ldg(d1 + off)), c_mone);
                }
                win[j & 31] = v;
            }
        }
    }
    {
        ull w96 = sw[96];
#pragma unroll
        for (int r = 0; r < R; r++)
            acc[r] = ffma2u(w96, win[(96 + r) & 31], acc[r]);
    }

#pragma unroll
    for (int r = 0; r < R; r++)
        ((ull*)g_tmp)[(size_t)(y0 + r) * WIDTH + x] = acc[r];
}

// ============ K2: horizontal blur + bilinear sample, warp-private ============
// Each warp owns a 512-px segment of the row (+48 halo each side = 608 u64,
// exactly 19 coalesced LDG.64 per lane). The segment lives in the warp's own
// skewed smem region; conv window refills are single LDS.64; the blurred field
// is stored back into the segment and sampled with lane-consecutive x.
// Only __syncwarp() between phases — no block barriers after the prologue.
__device__ __forceinline__ int sk(int p) { return p + (p >> 4); }
#define SEG_PX  512
#define SEG_LD  608                  // 512 + 2*RAD = 19*32
#define SEGU    648                  // sk(607)=644 < 648 (u64 slots, 8B skew units)

__global__ void __launch_bounds__(128) hblur_sample_kernel(
    const float* __restrict__ img, const float* __restrict__ msk,
    float* __restrict__ out,
    const float* __restrict__ log_sigma, const float* __restrict__ log_alpha) {
    __shared__ ull sw[KS];
    __shared__ float e0s[KS], e1s[KS], sums[2];
    __shared__ ull sseg[4][SEGU];
    build_weights(sw, log_sigma, log_alpha, true, e0s, e1s, sums);

    int tid  = threadIdx.x;
    int lane = tid & 31;
    int wid  = tid >> 5;
    int y    = blockIdx.x;
    int segx = wid * SEG_PX;                        // global x of segment start
    ull* S = sseg[wid];
    const ull* trow = ((const ull*)g_tmp) + (size_t)y * WIDTH;

    // Phase 1 (per-warp): load segment + halo, zero outside row
#pragma unroll
    for (int i = 0; i < SEG_LD / 32; i++) {
        int p  = i * 32 + lane;
        int gx = segx + p - RAD;
        ull v = 0ull;
        if ((unsigned)gx < (unsigned)WIDTH) v = __ldg(trow + gx);
        S[sk(p)] = v;
    }
    __syncwarp();

    // Phase 2 (per-warp): 97-tap conv, 32-slot register window
    int x0 = lane * R;                              // local position in segment
    ull acc[R];
#pragma unroll
    for (int r = 0; r < R; r++) acc[r] = 0ull;

    ull win[32];
#pragma unroll
    for (int k = 0; k < 32; k++) win[k] = S[sk(x0 + k)];

#pragma unroll
    for (int J = 0; J < 96; J += 16) {
#pragma unroll
        for (int jj = 0; jj < 16; jj++) {
            const int j = J + jj;
            ull wj = sw[j];
#pragma unroll
            for (int r = 0; r < R; r++)
                acc[r] = ffma2u(wj, win[(j + r) & 31], acc[r]);
            if (J < 80) win[j & 31] = S[sk(x0 + j + 32)];
        }
    }
    {
        ull w96 = sw[96];
#pragma unroll
        for (int r = 0; r < R; r++)
            acc[r] = ffma2u(w96, win[(96 + r) & 31], acc[r]);
    }
    __syncwarp();   // all lanes done reading the segment

    // Phase 3 (per-warp): store blurred field at local output positions [0,512)
#pragma unroll
    for (int r = 0; r < R; r++) S[sk(x0 + r)] = acc[r];
    __syncwarp();

    // Phase 4 (per-warp): bilinear sample, lane-consecutive x
    const float gy = (float)y * (2.0f / (HEIGHT - 1)) - 1.0f;
    size_t rowoff = (size_t)y * WIDTH;

#pragma unroll 2
    for (int k = 0; k < R; k++) {
        int lp = lane + k * 32;
        int x  = segx + lp;
        float dxf, dyf;
        unpackf2(S[sk(lp)], dxf, dyf);
        float gx = (float)x * (2.0f / (WIDTH - 1)) - 1.0f;
        // reference: x-coord gets blurred ch0 (dy), y-coord gets blurred ch1 (dx)
        float sx = fminf(fmaxf(gx + dxf, -1.0f), 1.0f);
        float sy = fminf(fmaxf(gy + dyf, -1.0f), 1.0f);
        float px = (sx + 1.0f) * 0.5f * (float)(WIDTH - 1);
        float py = (sy + 1.0f) * 0.5f * (float)(HEIGHT - 1);
        float fx = floorf(px), fy = floorf(py);
        float wx = px - fx,    wy = py - fy;
        int ix0 = (int)fx;
        int iy0 = (int)fy;
        int ix1 = min(ix0 + 1, WIDTH - 1);
        int iy1 = min(iy0 + 1, HEIGHT - 1);
        size_t o00 = (size_t)iy0 * WIDTH + ix0;
        size_t o01 = (size_t)iy0 * WIDTH + ix1;
        size_t o10 = (size_t)iy1 * WIDTH + ix0;
        size_t o11 = (size_t)iy1 * WIDTH + ix1;
#pragma unroll
        for (int c = 0; c < 4; c++) {
            const float* src = (c < 3) ? (img + (size_t)c * HW) : msk;
            float v00 = __ldg(src + o00);
            float v01 = __ldg(src + o01);
            float v10 = __ldg(src + o10);
            float v11 = __ldg(src + o11);
            float top = v00 * (1.0f - wx) + v01 * wx;
            float bot = v10 * (1.0f - wx) + v11 * wx;
            out[(size_t)c * HW + rowoff + x] = top * (1.0f - wy) + bot * wy;
        }
    }
}

// ---------------- launch ----------------
extern "C" void kernel_launch(void* const* d_in, const int* in_sizes, int n_in,
                              void* d_out, int out_size) {
    const float* image     = (const float*)d_in[0];  // (3, H, W)
    const float* mask      = (const float*)d_in[1];  // (1, H, W)
    const float* drand     = (const float*)d_in[2];  // (1, 2, H, W)
    const float* log_sigma = (const float*)d_in[3];  // (2,)
    const float* log_alpha = (const float*)d_in[4];  // (2,)
    float* out = (float*)d_out;                      // img(3HW) then mask(HW)

    vblur_kernel<<<dim3(WIDTH / 256, HEIGHT / R), 256>>>(drand, log_sigma, log_alpha);
    hblur_sample_kernel<<<HEIGHT, 128>>>(image, mask, out, log_sigma, log_alpha);
}

// round 13
// speedup vs baseline: 2.5030x; 1.4528x over previous
#include <cuda_runtime.h>

#define WIDTH  2048
#define HEIGHT 2048
#define HW (2048 * 2048)
#define KS  97
#define RAD 48
#define R   8           // outputs per thread (both passes)
#define WSL 16          // register-window slots
#define NIN 104         // inputs consumed per thread: R + 2*RAD

typedef unsigned long long ull;

// ---------------- device scratch (no allocations allowed) ----------------
__device__ float2 g_tmp[HW];   // vertically blurred field, interleaved (ch0, ch1)

// ---------------- packed fp32x2 ops, u64-native ----------------
__device__ __forceinline__ ull packf2(float lo, float hi) {
    ull u;
    asm("mov.b64 %0, {%1, %2};" : "=l"(u) : "f"(lo), "f"(hi));
    return u;
}
__device__ __forceinline__ void unpackf2(ull u, float& lo, float& hi) {
    asm("mov.b64 {%0, %1}, %2;" : "=f"(lo), "=f"(hi) : "l"(u));
}
__device__ __forceinline__ ull ffma2u(ull a, ull b, ull c) {
    ull d;
    asm("fma.rn.f32x2 %0, %1, %2, %3;" : "=l"(d) : "l"(a), "l"(b), "l"(c));
    return d;
}

// ---------------- inline weight table build (per-block, deterministic) ------
__device__ __forceinline__ void build_weights(
    ull* sw, const float* __restrict__ log_sigma, const float* __restrict__ log_alpha,
    bool mul_alpha, float* e0s, float* e1s, float* sums) {
    int t = threadIdx.x;
    float s0 = expf(log_sigma[0]);
    float s1 = expf(log_sigma[1]);
    if (t < KS) {
        float x = (float)(t - KS / 2);
        e0s[t] = expf(-x * x / (2.0f * s0 * s0));
        e1s[t] = expf(-x * x / (2.0f * s1 * s1));
    }
    __syncthreads();
    if (t == 0) {
        float a = 0.f, b = 0.f;
        for (int i = 0; i < KS; i++) { a += e0s[i]; b += e1s[i]; }
        sums[0] = a; sums[1] = b;
    }
    __syncthreads();
    if (t < KS) {
        float w0 = e0s[t] / sums[0];
        float w1 = e1s[t] / sums[1];
        if (mul_alpha) {
            w0 *= expf(log_alpha[0]);
            w1 *= expf(log_alpha[1]);
        }
        sw[t] = packf2(w0, w1);
    }
    __syncthreads();
}

// ================= K1: vertical blur (both channels packed) =================
// 97-tap FIR, 8 outputs/thread, 16-slot u64 register window (fits registers,
// NO spills). Window invariant: before tap j, slots hold in[j..j+15].
// Refill at tap j loads in[j+16]; guarded by J<88 so exactly in[0..103] load.
__global__ void __launch_bounds__(256) vblur_kernel(
    const float* __restrict__ drand,
    const float* __restrict__ log_sigma, const float* __restrict__ log_alpha) {
    __shared__ ull sw[KS];
    __shared__ float e0s[KS], e1s[KS], sums[2];
    build_weights(sw, log_sigma, log_alpha, false, e0s, e1s, sums);

    int tid = threadIdx.x;
    int x  = blockIdx.x * 256 + tid;
    int y0 = blockIdx.y * R;

    const float* d0 = drand;
    const float* d1 = drand + HW;
    const ull c_two  = packf2(2.f, 2.f);
    const ull c_mone = packf2(-1.f, -1.f);

    ull acc[R];
#pragma unroll
    for (int r = 0; r < R; r++) acc[r] = 0ull;   // packed (0,0)

    ull win[WSL];
#pragma unroll
    for (int k = 0; k < WSL; k++) {
        int iy = y0 - RAD + k;
        ull v = 0ull;
        if ((unsigned)iy < (unsigned)HEIGHT) {
            size_t off = (size_t)iy * WIDTH + x;
            v = ffma2u(c_two, packf2(__ldg(d0 + off), __ldg(d1 + off)), c_mone);
        }
        win[k] = v;
    }

#pragma unroll
    for (int J = 0; J < 96; J += 8) {
#pragma unroll
        for (int jj = 0; jj < 8; jj++) {
            const int j = J + jj;
            ull wj = sw[j];
#pragma unroll
            for (int r = 0; r < R; r++)
                acc[r] = ffma2u(wj, win[(j + r) & (WSL - 1)], acc[r]);
            if (J < 88) {
                int iy = y0 - RAD + j + WSL;
                ull v = 0ull;
                if ((unsigned)iy < (unsigned)HEIGHT) {
                    size_t off = (size_t)iy * WIDTH + x;
                    v = ffma2u(c_two, packf2(__ldg(d0 + off), __ldg(d1 + off)), c_mone);
                }
                win[j & (WSL - 1)] = v;
            }
        }
    }
    {
        ull w96 = sw[96];
#pragma unroll
        for (int r = 0; r < R; r++)
            acc[r] = ffma2u(w96, win[(96 + r) & (WSL - 1)], acc[r]);
    }

#pragma unroll
    for (int r = 0; r < R; r++)
        ((ull*)g_tmp)[(size_t)(y0 + r) * WIDTH + x] = acc[r];
}

// ============ K2: horizontal blur + bilinear sample, warp-private ============
// 256 threads / 8 warps, one row per block. Each warp owns a 256-px segment
// (+104 inputs span per lane: lane x0=lane*8, inputs x0..x0+103, max 351 ->
// 352 u64 = 11 coalesced LDG.64/lane). Conv uses the same 16-slot register
// window (no spills). Only __syncwarp() between phases.
__device__ __forceinline__ int sk(int p) { return p + (p >> 4); }
#define SEG_PX  256
#define SEG_LD  352                  // 256 + 2*RAD - ... = lane31 max input 351 +1
#define SEGU    376                  // sk(351)=372 < 376 (u64 slots)

__global__ void __launch_bounds__(256) hblur_sample_kernel(
    const float* __restrict__ img, const float* __restrict__ msk,
    float* __restrict__ out,
    const float* __restrict__ log_sigma, const float* __restrict__ log_alpha) {
    __shared__ ull sw[KS];
    __shared__ float e0s[KS], e1s[KS], sums[2];
    __shared__ ull sseg[8][SEGU];
    build_weights(sw, log_sigma, log_alpha, true, e0s, e1s, sums);

    int tid  = threadIdx.x;
    int lane = tid & 31;
    int wid  = tid >> 5;
    int y    = blockIdx.x;
    int segx = wid * SEG_PX;                        // global x of segment start
    ull* S = sseg[wid];
    const ull* trow = ((const ull*)g_tmp) + (size_t)y * WIDTH;

    // Phase 1 (per-warp): load segment + halo, zero outside row
#pragma unroll
    for (int i = 0; i < SEG_LD / 32; i++) {
        int p  = i * 32 + lane;
        int gx = segx + p - RAD;
        ull v = 0ull;
        if ((unsigned)gx < (unsigned)WIDTH) v = __ldg(trow + gx);
        S[sk(p)] = v;
    }
    __syncwarp();

    // Phase 2 (per-warp): 97-tap conv, 16-slot register window
    int x0 = lane * R;                              // local position in segment
    ull acc[R];
#pragma unroll
    for (int r = 0; r < R; r++) acc[r] = 0ull;

    ull win[WSL];
#pragma unroll
    for (int k = 0; k < WSL; k++) win[k] = S[sk(x0 + k)];

#pragma unroll
    for (int J = 0; J < 96; J += 8) {
#pragma unroll
        for (int jj = 0; jj < 8; jj++) {
            const int j = J + jj;
            ull wj = sw[j];
#pragma unroll
            for (int r = 0; r < R; r++)
                acc[r] = ffma2u(wj, win[(j + r) & (WSL - 1)], acc[r]);
            if (J < 88) win[j & (WSL - 1)] = S[sk(x0 + j + WSL)];
        }
    }
    {
        ull w96 = sw[96];
#pragma unroll
        for (int r = 0; r < R; r++)
            acc[r] = ffma2u(w96, win[(96 + r) & (WSL - 1)], acc[r]);
    }
    __syncwarp();   // all lanes done reading the segment

    // Phase 3 (per-warp): store blurred field at local output positions [0,256)
#pragma unroll
    for (int r = 0; r < R; r++) S[sk(x0 + r)] = acc[r];
    __syncwarp();

    // Phase 4 (per-warp): bilinear sample, lane-consecutive x
    const float gy = (float)y * (2.0f / (HEIGHT - 1)) - 1.0f;
    size_t rowoff = (size_t)y * WIDTH;

#pragma unroll 2
    for (int k = 0; k < R; k++) {
        int lp = lane + k * 32;
        int x  = segx + lp;
        float dxf, dyf;
        unpackf2(S[sk(lp)], dxf, dyf);
        float gx = (float)x * (2.0f / (WIDTH - 1)) - 1.0f;
        // reference: x-coord gets blurred ch0 (dy), y-coord gets blurred ch1 (dx)
        float sx = fminf(fmaxf(gx + dxf, -1.0f), 1.0f);
        float sy = fminf(fmaxf(gy + dyf, -1.0f), 1.0f);
        float px = (sx + 1.0f) * 0.5f * (float)(WIDTH - 1);
        float py = (sy + 1.0f) * 0.5f * (float)(HEIGHT - 1);
        float fx = floorf(px), fy = floorf(py);
        float wx = px - fx,    wy = py - fy;
        int ix0 = (int)fx;
        int iy0 = (int)fy;
        int ix1 = min(ix0 + 1, WIDTH - 1);
        int iy1 = min(iy0 + 1, HEIGHT - 1);
        size_t o00 = (size_t)iy0 * WIDTH + ix0;
        size_t o01 = (size_t)iy0 * WIDTH + ix1;
        size_t o10 = (size_t)iy1 * WIDTH + ix0;
        size_t o11 = (size_t)iy1 * WIDTH + ix1;
#pragma unroll
        for (int c = 0; c < 4; c++) {
            const float* src = (c < 3) ? (img + (size_t)c * HW) : msk;
            float v00 = __ldg(src + o00);
            float v01 = __ldg(src + o01);
            float v10 = __ldg(src + o10);
            float v11 = __ldg(src + o11);
            float top = v00 * (1.0f - wx) + v01 * wx;
            float bot = v10 * (1.0f - wx) + v11 * wx;
            out[(size_t)c * HW + rowoff + x] = top * (1.0f - wy) + bot * wy;
        }
    }
}

// ---------------- launch ----------------
extern "C" void kernel_launch(void* const* d_in, const int* in_sizes, int n_in,
                              void* d_out, int out_size) {
    const float* image     = (const float*)d_in[0];  // (3, H, W)
    const float* mask      = (const float*)d_in[1];  // (1, H, W)
    const float* drand     = (const float*)d_in[2];  // (1, 2, H, W)
    const float* log_sigma = (const float*)d_in[3];  // (2,)
    const float* log_alpha = (const float*)d_in[4];  // (2,)
    float* out = (float*)d_out;                      // img(3HW) then mask(HW)

    vblur_kernel<<<dim3(WIDTH / 256, HEIGHT / R), 256>>>(drand, log_sigma, log_alpha);
    hblur_sample_kernel<<<HEIGHT, 256>>>(image, mask, out, log_sigma, log_alpha);
}

// round 14
// speedup vs baseline: 2.9447x; 1.1764x over previous
#include <cuda_runtime.h>

#define WIDTH  2048
#define HEIGHT 2048
#define HW (2048 * 2048)
#define KS  97
#define RAD 48

typedef unsigned long long ull;

// ---------------- device scratch (no allocations allowed) ----------------
__device__ float2 g_tmp[HW];   // vertically blurred field, interleaved (ch0, ch1)

// ---------------- packed fp32x2 ops, u64-native ----------------
__device__ __forceinline__ ull packf2(float lo, float hi) {
    ull u;
    asm("mov.b64 %0, {%1, %2};" : "=l"(u) : "f"(lo), "f"(hi));
    return u;
}
__device__ __forceinline__ void unpackf2(ull u, float& lo, float& hi) {
    asm("mov.b64 {%0, %1}, %2;" : "=f"(lo), "=f"(hi) : "l"(u));
}
__device__ __forceinline__ ull ffma2u(ull a, ull b, ull c) {
    ull d;
    asm("fma.rn.f32x2 %0, %1, %2, %3;" : "=l"(d) : "l"(a), "l"(b), "l"(c));
    return d;
}

// ---------------- inline weight table build (per-block, deterministic) ------
__device__ __forceinline__ void build_weights(
    ull* sw, const float* __restrict__ log_sigma, const float* __restrict__ log_alpha,
    bool mul_alpha, float* e0s, float* e1s, float* sums) {
    int t = threadIdx.x;
    float s0 = expf(log_sigma[0]);
    float s1 = expf(log_sigma[1]);
    if (t < KS) {
        float x = (float)(t - KS / 2);
        e0s[t] = expf(-x * x / (2.0f * s0 * s0));
        e1s[t] = expf(-x * x / (2.0f * s1 * s1));
    }
    __syncthreads();
    if (t == 0) {
        float a = 0.f, b = 0.f;
        for (int i = 0; i < KS; i++) { a += e0s[i]; b += e1s[i]; }
        sums[0] = a; sums[1] = b;
    }
    __syncthreads();
    if (t < KS) {
        float w0 = e0s[t] / sums[0];
        float w1 = e1s[t] / sums[1];
        if (mul_alpha) {
            w0 *= expf(log_alpha[0]);
            w1 *= expf(log_alpha[1]);
        }
        sw[t] = packf2(w0, w1);
    }
    __syncthreads();
}

// ================= K1: vertical blur, smem-staged column tile =================
// Block = 256 threads = 32 cols x 8 row-groups; output tile 32 cols x 64 rows.
// Input window (160 rows x 32 cols, as 2d-1) staged ONCE into transposed smem
// (stride 163 u64: 3c mod 16 distinct -> conflict-free), killing the 13x L2
// read redundancy of the unstaged version. Conv: R=8, 16-slot register window.
#define VR    8
#define VROWS 64
#define VIN   160              // VROWS + 2*RAD
#define VSTR  163              // smem row stride per column (u64), odd*... 3c%16 distinct

__global__ void __launch_bounds__(256) vblur_kernel(
    const float* __restrict__ drand,
    const float* __restrict__ log_sigma, const float* __restrict__ log_alpha) {
    __shared__ ull sw[KS];
    __shared__ float e0s[KS], e1s[KS], sums[2];
    __shared__ ull tile[32 * VSTR];
    build_weights(sw, log_sigma, log_alpha, false, e0s, e1s, sums);

    int tid = threadIdx.x;
    int gx0 = blockIdx.x * 32;
    int y0  = blockIdx.y * VROWS;

    const float* d0 = drand;
    const float* d1 = drand + HW;
    const ull c_two  = packf2(2.f, 2.f);
    const ull c_mone = packf2(-1.f, -1.f);

    // stage input window: gmem coalesced reads, transposed conflict-free STS
#pragma unroll
    for (int it = 0; it < VIN * 32 / 256; it++) {
        int i   = it * 256 + tid;
        int row = i >> 5;              // 0..159
        int col = i & 31;
        int iy  = y0 - RAD + row;
        ull v = 0ull;
        if ((unsigned)iy < (unsigned)HEIGHT) {
            size_t off = (size_t)iy * WIDTH + gx0 + col;
            v = ffma2u(c_two, packf2(__ldg(d0 + off), __ldg(d1 + off)), c_mone);
        }
        tile[col * VSTR + row] = v;
    }
    __syncthreads();

    int c = tid & 31;
    int g = tid >> 5;                  // row-group: outputs y0+g*8 .. +7
    const ull* T = tile + c * VSTR + g * VR;   // T[m] = input (y0-48+g*8+m, col)

    ull acc[VR];
#pragma unroll
    for (int r = 0; r < VR; r++) acc[r] = 0ull;

    ull win[16];
#pragma unroll
    for (int k = 0; k < 16; k++) win[k] = T[k];

#pragma unroll
    for (int J = 0; J < 96; J += 8) {
#pragma unroll
        for (int jj = 0; jj < 8; jj++) {
            const int j = J + jj;
            ull wj = sw[j];
#pragma unroll
            for (int r = 0; r < VR; r++)
                acc[r] = ffma2u(wj, win[(j + r) & 15], acc[r]);
            if (J < 88) win[j & 15] = T[j + 16];
        }
    }
    {
        ull w96 = sw[96];
#pragma unroll
        for (int r = 0; r < VR; r++)
            acc[r] = ffma2u(w96, win[(96 + r) & 15], acc[r]);
    }

#pragma unroll
    for (int r = 0; r < VR; r++)
        ((ull*)g_tmp)[(size_t)(y0 + g * VR + r) * WIDTH + gx0 + c] = acc[r];
}

// ============ K2: horizontal blur + bilinear sample, warp-private ============
// 256 threads / 8 warps; warps 0-3 own row y0 (512-px segments), warps 4-7 row
// y0+1. R=16 per lane: x0 = lane*16 makes the skewed smem addressing AFFINE
// (sk(x0+m) = lane*17 + m + (m>>4)) -> window LDS are immediate-offset, and
// LDS/output drops to 7. Only __syncwarp() between phases.
__device__ __forceinline__ int sk(int p) { return p + (p >> 4); }
#define HR      16
#define SEG_PX  512
#define SEG_LD  608                  // inputs 0..607 (max lane: 31*16+111)
#define SEGU    648                  // sk(607)=644 < 648 (u64 slots)

__global__ void __launch_bounds__(256, 1) hblur_sample_kernel(
    const float* __restrict__ img, const float* __restrict__ msk,
    float* __restrict__ out,
    const float* __restrict__ log_sigma, const float* __restrict__ log_alpha) {
    __shared__ ull sw[KS];
    __shared__ float e0s[KS], e1s[KS], sums[2];
    __shared__ ull sseg[8][SEGU];
    build_weights(sw, log_sigma, log_alpha, true, e0s, e1s, sums);

    int tid  = threadIdx.x;
    int lane = tid & 31;
    int wid  = tid >> 5;
    int y    = blockIdx.x * 2 + (wid >> 2);
    int segx = (wid & 3) * SEG_PX;                  // global x of segment start
    ull* S = sseg[wid];
    const ull* trow = ((const ull*)g_tmp) + (size_t)y * WIDTH;

    // Phase 1 (per-warp): load segment + halo, zero outside row
#pragma unroll
    for (int i = 0; i < SEG_LD / 32; i++) {
        int p  = i * 32 + lane;
        int gx = segx + p - RAD;
        ull v = 0ull;
        if ((unsigned)gx < (unsigned)WIDTH) v = __ldg(trow + gx);
        S[sk(p)] = v;
    }
    __syncwarp();

    // Phase 2 (per-warp): 97-tap conv, 16-slot register window, R=16
    int x0 = lane * HR;
    ull acc[HR];
#pragma unroll
    for (int r = 0; r < HR; r++) acc[r] = 0ull;

    ull win[16];
#pragma unroll
    for (int k = 0; k < 16; k++) win[k] = S[sk(x0 + k)];

#pragma unroll
    for (int J = 0; J < 96; J += 8) {
#pragma unroll
        for (int jj = 0; jj < 8; jj++) {
            const int j = J + jj;
            ull wj = sw[j];
#pragma unroll
            for (int r = 0; r < HR; r++)
                acc[r] = ffma2u(wj, win[(j + r) & 15], acc[r]);
            win[j & 15] = S[sk(x0 + j + 16)];   // loads inputs 16..111
        }
    }
    {
        ull w96 = sw[96];
#pragma unroll
        for (int r = 0; r < HR; r++)
            acc[r] = ffma2u(w96, win[(96 + r) & 15], acc[r]);
    }
    __syncwarp();   // all lanes done reading the segment

    // Phase 3 (per-warp): store blurred field at local output positions [0,512)
#pragma unroll
    for (int r = 0; r < HR; r++) S[sk(x0 + r)] = acc[r];
    __syncwarp();

    // Phase 4 (per-warp): bilinear sample, lane-consecutive x
    const float gy = (float)y * (2.0f / (HEIGHT - 1)) - 1.0f;
    size_t rowoff = (size_t)y * WIDTH;

#pragma unroll 2
    for (int k = 0; k < HR; k++) {
        int lp = lane + k * 32;
        int x  = segx + lp;
        float dxf, dyf;
        unpackf2(S[sk(lp)], dxf, dyf);
        float gx = (float)x * (2.0f / (WIDTH - 1)) - 1.0f;
        // reference: x-coord gets blurred ch0 (dy), y-coord gets blurred ch1 (dx)
        float sx = fminf(fmaxf(gx + dxf, -1.0f), 1.0f);
        float sy = fminf(fmaxf(gy + dyf, -1.0f), 1.0f);
        float px = (sx + 1.0f) * 0.5f * (float)(WIDTH - 1);
        float py = (sy + 1.0f) * 0.5f * (float)(HEIGHT - 1);
        float fx = floorf(px), fy = floorf(py);
        float wx = px - fx,    wy = py - fy;
        int ix0 = (int)fx;
        int iy0 = (int)fy;
        int ix1 = min(ix0 + 1, WIDTH - 1);
        int iy1 = min(iy0 + 1, HEIGHT - 1);
        size_t o00 = (size_t)iy0 * WIDTH + ix0;
        size_t o01 = (size_t)iy0 * WIDTH + ix1;
        size_t o10 = (size_t)iy1 * WIDTH + ix0;
        size_t o11 = (size_t)iy1 * WIDTH + ix1;
#pragma unroll
        for (int c = 0; c < 4; c++) {
            const float* src = (c < 3) ? (img + (size_t)c * HW) : msk;
            float v00 = __ldg(src + o00);
            float v01 = __ldg(src + o01);
            float v10 = __ldg(src + o10);
            float v11 = __ldg(src + o11);
            float top = v00 * (1.0f - wx) + v01 * wx;
            float bot = v10 * (1.0f - wx) + v11 * wx;
            out[(size_t)c * HW + rowoff + x] = top * (1.0f - wy) + bot * wy;
        }
    }
}

// ---------------- launch ----------------
extern "C" void kernel_launch(void* const* d_in, const int* in_sizes, int n_in,
                              void* d_out, int out_size) {
    const float* image     = (const float*)d_in[0];  // (3, H, W)
    const float* mask      = (const float*)d_in[1];  // (1, H, W)
    const float* drand     = (const float*)d_in[2];  // (1, 2, H, W)
    const float* log_sigma = (const float*)d_in[3];  // (2,)
    const float* log_alpha = (const float*)d_in[4];  // (2,)
    float* out = (float*)d_out;                      // img(3HW) then mask(HW)

    vblur_kernel<<<dim3(WIDTH / 32, HEIGHT / VROWS), 256>>>(drand, log_sigma, log_alpha);
    hblur_sample_kernel<<<HEIGHT / 2, 256>>>(image, mask, out, log_sigma, log_alpha);
}